// round 9
// baseline (speedup 1.0000x reference)
#include <cuda_runtime.h>
#include <cuda_bf16.h>
#include <stdint.h>

// CAM_Module: x (16,512,64,64) fp32, gamma (1,) fp32 == 0 in this benchmark.
// out = gamma * channel_attention(x) + x.
//
// SINGLE-KERNEL, branch-free fast path. Measured-best geometry: 2x float4
// per thread, 16384 blocks, DEFAULT loads (preserve x's cross-replay L2
// residency — x is 134MB vs 126MB L2 and ncu shows ~20% of traffic served
// from L2) + EVICT-FIRST (__stcs) stores (minimize out's write-allocate
// pollution of x's L2 lines). Heavy gamma != 0 path (never taken here) runs
// per-row inside the same kernel behind a uniform branch.

#define BATCH 16
#define CHN   512
#define NPIX  4096                       // 64*64
#define ROWS  (BATCH * CHN)              // 8192
#define CHUNK 2048                       // floats per block (half row)
#define NBLK  (ROWS * 2)                 // 16384 blocks

__global__ void __launch_bounds__(256, 8)
cam_kernel(const float* __restrict__ x,
           const float* __restrict__ gamma,
           float* __restrict__ out) {
    const int t = threadIdx.x;

    // ---- Fast path: unconditional copy, no gamma dependency ----
    // Default loads (keep x hot in L2 across graph replays);
    // evict-first stores (don't let out's write-allocate evict x).
    const long base4 = ((long)blockIdx.x * 256 + t) * 2;  // float4 index
    const float4* x4 = reinterpret_cast<const float4*>(x);
    float4* out4 = reinterpret_cast<float4*>(out);

    float4 v0 = x4[base4 + 0];
    float4 v1 = x4[base4 + 1];
    __stcs(&out4[base4 + 0], v0);
    __stcs(&out4[base4 + 1], v1);

    // gamma load overlaps the copy; uniform branch.
    const float g = __ldg(gamma);
    if (g == 0.0f) return;

    // ---- Heavy path (correctness-only; never runs when gamma == 0) ----
    __shared__ float sh_e[CHN];          // energy row -> attention row
    __shared__ float red[256];

    const int blk = blockIdx.x;
    const int row  = blk >> 1;           // (b,c) row index
    const int half = blk & 1;            // which 2048-float chunk
    const int b = row >> 9;              // row / CHN
    const int c = row & (CHN - 1);       // row % CHN
    const float* vb = x + (long)b * CHN * NPIX;   // v[b] : CHN x NPIX
    const float* vc = vb + (long)c * NPIX;

    // energy[d] = <v[b,c,:], v[b,d,:]>
    for (int d = t; d < CHN; d += 256) {
        const float* vd = vb + (long)d * NPIX;
        float s = 0.0f;
        #pragma unroll 4
        for (int n = 0; n < NPIX; ++n) s = fmaf(vc[n], vd[n], s);
        sh_e[d] = s;
    }
    __syncthreads();

    // min over the row (softmax(max - e) == exp(min - e)/sum)
    float mn = 3.402823e38f;
    for (int d = t; d < CHN; d += 256) mn = fminf(mn, sh_e[d]);
    red[t] = mn; __syncthreads();
    for (int s = 128; s > 0; s >>= 1) {
        if (t < s) red[t] = fminf(red[t], red[t + s]);
        __syncthreads();
    }
    mn = red[0]; __syncthreads();

    // exponentiate + sum
    float sum = 0.0f;
    for (int d = t; d < CHN; d += 256) {
        float ex = __expf(mn - sh_e[d]);
        sh_e[d] = ex;
        sum += ex;
    }
    red[t] = sum; __syncthreads();
    for (int s = 128; s > 0; s >>= 1) {
        if (t < s) red[t] += red[t + s];
        __syncthreads();
    }
    const float inv = 1.0f / red[0];
    __syncthreads();
    for (int d = t; d < CHN; d += 256) sh_e[d] *= inv;
    __syncthreads();

    // out[n] = x[n] + g * sum_d attn[d] * v[b,d,n] for my 8 n's
    const int n0 = half * CHUNK + t * 8;
    float acc[8];
    #pragma unroll
    for (int j = 0; j < 8; ++j) acc[j] = 0.0f;
    for (int d = 0; d < CHN; ++d) {
        const float a = sh_e[d];
        const float* vdn = vb + (long)d * NPIX + n0;
        #pragma unroll
        for (int j = 0; j < 8; ++j) acc[j] = fmaf(a, vdn[j], acc[j]);
    }
    v0.x = fmaf(g, acc[0], v0.x); v0.y = fmaf(g, acc[1], v0.y);
    v0.z = fmaf(g, acc[2], v0.z); v0.w = fmaf(g, acc[3], v0.w);
    v1.x = fmaf(g, acc[4], v1.x); v1.y = fmaf(g, acc[5], v1.y);
    v1.z = fmaf(g, acc[6], v1.z); v1.w = fmaf(g, acc[7], v1.w);
    out4[base4 + 0] = v0;
    out4[base4 + 1] = v1;
}

extern "C" void kernel_launch(void* const* d_in, const int* in_sizes, int n_in,
                              void* d_out, int out_size) {
    // Identify inputs by element count (x has 33.5M elements, gamma has 1).
    const float* x = (const float*)d_in[0];
    const float* gamma = (const float*)d_in[1];
    if (n_in >= 2 && in_sizes[0] == 1) {
        gamma = (const float*)d_in[0];
        x = (const float*)d_in[1];
    }
    float* out = (float*)d_out;

    // One kernel, one graph node. 16384 blocks x 256 threads x 8 floats
    // = 33,554,432 elements, exact cover.
    cam_kernel<<<NBLK, 256>>>(x, gamma, out);
}